// round 14
// baseline (speedup 1.0000x reference)
#include <cuda_runtime.h>
#include <cuda_fp16.h>

#define NPTS 100000
#define NSAMP 16
#define CCH 64
#define CWCH 8
#define NROW (NPTS * NSAMP)   // 1600000
#define BN_EPS 1e-5f

#define QKV_TILE 16
#define QKV_TILES 10
#define QKV_ROWS (QKV_TILE * QKV_TILES)   // 160
#define QKV_GRID (NPTS / QKV_ROWS)        // 625
#define QKV_THREADS 192

// raw-stat layout: bn1 at 0..2, bn2 at 4..67, bn3 at 68..75
#define BN2_OFF 4
#define BN3_OFF 68

// ---------------- scratch (__device__ globals: allocation-free, zero-init) ----
__device__ float g_xq[NPTS * CCH];
__device__ __align__(16) __half g_xk16[NPTS * CCH];   // fp16 gather table
__device__ __align__(16) __half g_xv16[NPTS * CCH];   // fp16 gather table
__device__ float g_w1[NROW * CWCH];
__device__ __align__(16) float4 g_p4[NPTS];
__device__ double g_sum[80];
__device__ double g_sqs[80];

// load 4 consecutive fp16 channels -> float4 (one LDG.64)
__device__ __forceinline__ float4 ld_half4(const __half* base) {
    uint2 raw = *reinterpret_cast<const uint2*>(base);
    __half2 h01 = *reinterpret_cast<__half2*>(&raw.x);
    __half2 h23 = *reinterpret_cast<__half2*>(&raw.y);
    float2 f01 = __half22float2(h01);
    float2 f23 = __half22float2(h23);
    return make_float4(f01.x, f01.y, f23.x, f23.y);
}

// per-block BN finalize from raw stats into shared (deterministic, redundant)
__device__ __forceinline__ void bn_to_shared(int off, int nch,
        const float* __restrict__ gamma, const float* __restrict__ beta,
        float* s_a, float* s_c) {
    int i = threadIdx.x;
    if (i < nch) {
        double m = g_sum[off + i] / (double)NROW;
        double v = g_sqs[off + i] / (double)NROW - m * m;
        float a = gamma[i] * rsqrtf((float)v + BN_EPS);
        s_a[i] = a;
        s_c[i] = beta[i] - a * (float)m;
    }
}

// ---------------- k_zero: zero stats for this replay ----------------
__global__ void k_zero() {
    int t = threadIdx.x;
    if (t < 80) { g_sum[t] = 0.0; g_sqs[t] = 0.0; }
}

// ---------------- k_pad: p -> g_p4 (float4-padded) ----------------
__global__ __launch_bounds__(256) void k_pad(const float* __restrict__ p) {
    int i = blockIdx.x * 256 + threadIdx.x;
    if (i < NPTS)
        g_p4[i] = make_float4(p[3 * i], p[3 * i + 1], p[3 * i + 2], 0.f);
}

// ---------------- k_p1: bn1 stats over t1 = p_r0 @ Wp1 + bp1 ----------------
__global__ __launch_bounds__(256) void k_p1(
    const int* __restrict__ idx,
    const float* __restrict__ Wp1, const float* __restrict__ bp1) {
    __shared__ float ss[3], sq[3];
    int tid = threadIdx.x;
    if (tid < 3) { ss[tid] = 0.f; sq[tid] = 0.f; }
    __syncthreads();
    int row = blockIdx.x * 256 + tid;
    int n = row >> 4;
    int j = idx[row];
    float4 pj = g_p4[j];
    float4 pn = g_p4[n];
    float dx = pj.x - pn.x, dy = pj.y - pn.y, dz = pj.z - pn.z;
    float t0 = bp1[0] + dx * Wp1[0] + dy * Wp1[3] + dz * Wp1[6];
    float t1 = bp1[1] + dx * Wp1[1] + dy * Wp1[4] + dz * Wp1[7];
    float t2 = bp1[2] + dx * Wp1[2] + dy * Wp1[5] + dz * Wp1[8];
    float a0 = t0, a1 = t1, a2 = t2;
    float q0 = t0 * t0, q1 = t1 * t1, q2 = t2 * t2;
#pragma unroll
    for (int o = 16; o; o >>= 1) {
        a0 += __shfl_down_sync(0xffffffffu, a0, o);
        a1 += __shfl_down_sync(0xffffffffu, a1, o);
        a2 += __shfl_down_sync(0xffffffffu, a2, o);
        q0 += __shfl_down_sync(0xffffffffu, q0, o);
        q1 += __shfl_down_sync(0xffffffffu, q1, o);
        q2 += __shfl_down_sync(0xffffffffu, q2, o);
    }
    if ((tid & 31) == 0) {
        atomicAdd(&ss[0], a0); atomicAdd(&sq[0], q0);
        atomicAdd(&ss[1], a1); atomicAdd(&sq[1], q1);
        atomicAdd(&ss[2], a2); atomicAdd(&sq[2], q2);
    }
    __syncthreads();
    if (tid < 3) {
        atomicAdd(&g_sum[tid], (double)ss[tid]);
        atomicAdd(&g_sqs[tid], (double)sq[tid]);
    }
}

// ---- k_qkv: pure [N,64]x[64,192] GEMM, weights register-resident ----
__global__ __launch_bounds__(QKV_THREADS) void k_qkv(
    const float* __restrict__ x,
    const float* __restrict__ Wq, const float* __restrict__ bq,
    const float* __restrict__ Wk, const float* __restrict__ bk,
    const float* __restrict__ Wv, const float* __restrict__ bv) {
    __shared__ __align__(16) float xs[QKV_TILE][CCH];
    int c = threadIdx.x;             // 0..191

    const float* W; const float* b; int cc; int sect;
    if (c < 64)       { W = Wq; b = bq; cc = c;       sect = 0; }
    else if (c < 128) { W = Wk; b = bk; cc = c - 64;  sect = 1; }
    else              { W = Wv; b = bv; cc = c - 128; sect = 2; }

    float w[CCH];
#pragma unroll
    for (int j = 0; j < CCH; j++) w[j] = W[j * CCH + cc];
    float bb = b[cc];

    int rb0 = blockIdx.x * QKV_ROWS;
    for (int t = 0; t < QKV_TILES; t++) {
        int rb = rb0 + t * QKV_TILE;
        __syncthreads();
        for (int i = c; i < QKV_TILE * CCH / 4; i += QKV_THREADS) {
            int r = i >> 4, c4 = i & 15;
            *reinterpret_cast<float4*>(&xs[r][c4 * 4]) =
                *reinterpret_cast<const float4*>(&x[(rb + r) * CCH + c4 * 4]);
        }
        __syncthreads();

        float acc[QKV_TILE];
#pragma unroll
        for (int r = 0; r < QKV_TILE; r++) acc[r] = bb;
#pragma unroll
        for (int j4 = 0; j4 < 16; j4++) {
            float w0 = w[4 * j4], w1 = w[4 * j4 + 1], w2 = w[4 * j4 + 2], w3 = w[4 * j4 + 3];
#pragma unroll
            for (int r = 0; r < QKV_TILE; r++) {
                float4 xv = *reinterpret_cast<const float4*>(&xs[r][4 * j4]);
                acc[r] = fmaf(w0, xv.x, acc[r]);
                acc[r] = fmaf(w1, xv.y, acc[r]);
                acc[r] = fmaf(w2, xv.z, acc[r]);
                acc[r] = fmaf(w3, xv.w, acc[r]);
            }
        }
        if (sect == 0) {
#pragma unroll
            for (int r = 0; r < QKV_TILE; r++)
                g_xq[(rb + r) * CCH + cc] = acc[r];
        } else if (sect == 1) {
#pragma unroll
            for (int r = 0; r < QKV_TILE; r++)
                g_xk16[(rb + r) * CCH + cc] = __float2half_rn(acc[r]);
        } else {
#pragma unroll
            for (int r = 0; r < QKV_TILE; r++)
                g_xv16[(rb + r) * CCH + cc] = __float2half_rn(acc[r]);
        }
    }
}

// ---------------- k_p2: bn2 stats over r_qk (fp16 xk gathers) ----------------
__global__ __launch_bounds__(256) void k_p2(
    const int* __restrict__ idx,
    const float* __restrict__ Wp1, const float* __restrict__ bp1,
    const float* __restrict__ Wp2, const float* __restrict__ bp2,
    const float* __restrict__ gp, const float* __restrict__ betap) {
    __shared__ __align__(16) float s_wp2[3][CCH];
    __shared__ __align__(16) float s_bp2[CCH];
    __shared__ float s_sum[CCH], s_sq[CCH];
    __shared__ __align__(16) float4 s_uj[8][32];
    __shared__ float s_a1[4], s_c1[4];
    int tid = threadIdx.x;
    bn_to_shared(0, 3, gp, betap, s_a1, s_c1);
    if (tid < CCH) {
        s_wp2[0][tid] = Wp2[tid];
        s_wp2[1][tid] = Wp2[CCH + tid];
        s_wp2[2][tid] = Wp2[2 * CCH + tid];
        s_bp2[tid] = bp2[tid];
        s_sum[tid] = 0.f; s_sq[tid] = 0.f;
    }
    float w00 = Wp1[0], w01 = Wp1[1], w02 = Wp1[2];
    float w10 = Wp1[3], w11 = Wp1[4], w12 = Wp1[5];
    float w20 = Wp1[6], w21 = Wp1[7], w22 = Wp1[8];
    float b0 = bp1[0], b1 = bp1[1], b2 = bp1[2];
    __syncthreads();
    int warp = tid >> 5, lane = tid & 31;
    int base = blockIdx.x * 256 + warp * 32;   // 32 rows = 2 points
    // phase A: own row -> u, j in smem
    {
        int row = base + lane;
        int j_own = idx[row];
        float4 pj = g_p4[j_own];
        float4 pn = g_p4[row >> 4];
        float dx = pj.x - pn.x, dy = pj.y - pn.y, dz = pj.z - pn.z;
        float t0 = b0 + dx * w00 + dy * w10 + dz * w20;
        float t1 = b1 + dx * w01 + dy * w11 + dz * w21;
        float t2 = b2 + dx * w02 + dy * w12 + dz * w22;
        float u0 = fmaxf(fmaf(s_a1[0], t0, s_c1[0]), 0.f);
        float u1 = fmaxf(fmaf(s_a1[1], t1, s_c1[1]), 0.f);
        float u2 = fmaxf(fmaf(s_a1[2], t2, s_c1[2]), 0.f);
        s_uj[warp][lane] = make_float4(u0, u1, u2, __int_as_float(j_own));
    }
    __syncwarp();
    // phase B: half-warp per point; lane owns channels cb..cb+3 (LDG.64 fp16)
    int half = lane >> 4;
    int cb = (lane & 15) * 4;
    int n0 = (base >> 4) + half;
    float4 wp0 = *reinterpret_cast<const float4*>(&s_wp2[0][cb]);
    float4 wp1 = *reinterpret_cast<const float4*>(&s_wp2[1][cb]);
    float4 wp2 = *reinterpret_cast<const float4*>(&s_wp2[2][cb]);
    float4 bbv = *reinterpret_cast<const float4*>(&s_bp2[cb]);
    {
        float4 qv = *reinterpret_cast<const float4*>(&g_xq[n0 * CCH + cb]);
        bbv.x -= qv.x; bbv.y -= qv.y; bbv.z -= qv.z; bbv.w -= qv.w;
    }
    float4 sum = make_float4(0.f, 0.f, 0.f, 0.f);
    float4 sq  = make_float4(0.f, 0.f, 0.f, 0.f);
#pragma unroll
    for (int r2 = 0; r2 < 16; r2++) {
        float4 uj = s_uj[warp][half * 16 + r2];
        int jr = __float_as_int(uj.w);
        float4 xk = ld_half4(&g_xk16[jr * CCH + cb]);
        float r0 = xk.x + fmaf(uj.x, wp0.x, fmaf(uj.y, wp1.x, fmaf(uj.z, wp2.x, bbv.x)));
        float r1 = xk.y + fmaf(uj.x, wp0.y, fmaf(uj.y, wp1.y, fmaf(uj.z, wp2.y, bbv.y)));
        float r2v= xk.z + fmaf(uj.x, wp0.z, fmaf(uj.y, wp1.z, fmaf(uj.z, wp2.z, bbv.z)));
        float r3 = xk.w + fmaf(uj.x, wp0.w, fmaf(uj.y, wp1.w, fmaf(uj.z, wp2.w, bbv.w)));
        sum.x += r0;  sq.x = fmaf(r0, r0, sq.x);
        sum.y += r1;  sq.y = fmaf(r1, r1, sq.y);
        sum.z += r2v; sq.z = fmaf(r2v, r2v, sq.z);
        sum.w += r3;  sq.w = fmaf(r3, r3, sq.w);
    }
    atomicAdd(&s_sum[cb],     sum.x); atomicAdd(&s_sq[cb],     sq.x);
    atomicAdd(&s_sum[cb + 1], sum.y); atomicAdd(&s_sq[cb + 1], sq.y);
    atomicAdd(&s_sum[cb + 2], sum.z); atomicAdd(&s_sq[cb + 2], sq.z);
    atomicAdd(&s_sum[cb + 3], sum.w); atomicAdd(&s_sq[cb + 3], sq.w);
    __syncthreads();
    if (tid < CCH) {
        atomicAdd(&g_sum[BN2_OFF + tid], (double)s_sum[tid]);
        atomicAdd(&g_sqs[BN2_OFF + tid], (double)s_sq[tid]);
    }
}

// ------- k_p3: w1 = relu(bn2(r_qk)) @ Ww1 + bww1, store + bn3 stats ---------
__global__ __launch_bounds__(128, 8) void k_p3(
    const int* __restrict__ idx,
    const float* __restrict__ Wp1, const float* __restrict__ bp1,
    const float* __restrict__ Wp2, const float* __restrict__ bp2,
    const float* __restrict__ Ww1, const float* __restrict__ bww1,
    const float* __restrict__ gp, const float* __restrict__ betap,
    const float* __restrict__ gw1, const float* __restrict__ bw1) {
    __shared__ __align__(16) float s_h[4][16][68];
    __shared__ __align__(16) float s_ww1[CCH * CWCH];
    __shared__ __align__(16) float s_wp2[3][CCH];
    __shared__ __align__(16) float s_bp2[CCH];
    __shared__ float s_ws[8], s_wq[8];
    __shared__ __align__(16) float4 s_uj[4][32];
    __shared__ float s_a1[4], s_c1[4];
    __shared__ __align__(16) float s_a2[CCH];
    __shared__ __align__(16) float s_c2[CCH];
    int tid = threadIdx.x;
    bn_to_shared(0, 3, gp, betap, s_a1, s_c1);
    bn_to_shared(BN2_OFF, CCH, gw1, bw1, s_a2, s_c2);
    for (int i = tid; i < CCH * CWCH; i += 128) s_ww1[i] = Ww1[i];
    if (tid < CCH) {
        s_wp2[0][tid] = Wp2[tid];
        s_wp2[1][tid] = Wp2[CCH + tid];
        s_wp2[2][tid] = Wp2[2 * CCH + tid];
        s_bp2[tid] = bp2[tid];
    }
    if (tid < 8) { s_ws[tid] = 0.f; s_wq[tid] = 0.f; }
    __syncthreads();
    int warp = tid >> 5, lane = tid & 31;
    int base = blockIdx.x * 128 + warp * 32;
    // phase A: all 32 rows of this warp
    {
        int row = base + lane;
        int j_own = idx[row];
        float4 pj = g_p4[j_own];
        float4 pn = g_p4[row >> 4];
        float dx = pj.x - pn.x, dy = pj.y - pn.y, dz = pj.z - pn.z;
        float t0 = bp1[0] + dx * Wp1[0] + dy * Wp1[3] + dz * Wp1[6];
        float t1 = bp1[1] + dx * Wp1[1] + dy * Wp1[4] + dz * Wp1[7];
        float t2 = bp1[2] + dx * Wp1[2] + dy * Wp1[5] + dz * Wp1[8];
        float u0 = fmaxf(fmaf(s_a1[0], t0, s_c1[0]), 0.f);
        float u1 = fmaxf(fmaf(s_a1[1], t1, s_c1[1]), 0.f);
        float u2 = fmaxf(fmaf(s_a1[2], t2, s_c1[2]), 0.f);
        s_uj[warp][lane] = make_float4(u0, u1, u2, __int_as_float(j_own));
    }
    __syncwarp();

#pragma unroll
    for (int tile = 0; tile < 2; tile++) {
        // phase B: one point (16 rows); half-warp covers 8 rows; lane owns 4 ch
        {
            int half = lane >> 4;
            int cb = (lane & 15) * 4;
            int nt = (base >> 4) + tile;
            float4 a2 = *reinterpret_cast<const float4*>(&s_a2[cb]);
            float4 c2 = *reinterpret_cast<const float4*>(&s_c2[cb]);
            float4 wp0 = *reinterpret_cast<const float4*>(&s_wp2[0][cb]);
            float4 wp1 = *reinterpret_cast<const float4*>(&s_wp2[1][cb]);
            float4 wp2 = *reinterpret_cast<const float4*>(&s_wp2[2][cb]);
            float4 bbv = *reinterpret_cast<const float4*>(&s_bp2[cb]);
            {
                float4 qv = *reinterpret_cast<const float4*>(&g_xq[nt * CCH + cb]);
                bbv.x -= qv.x; bbv.y -= qv.y; bbv.z -= qv.z; bbv.w -= qv.w;
            }
#pragma unroll
            for (int r2 = 0; r2 < 8; r2++) {
                int r = half * 8 + r2;
                float4 uj = s_uj[warp][tile * 16 + r];
                int jr = __float_as_int(uj.w);
                float4 xk = ld_half4(&g_xk16[jr * CCH + cb]);
                float r0 = xk.x + fmaf(uj.x, wp0.x, fmaf(uj.y, wp1.x, fmaf(uj.z, wp2.x, bbv.x)));
                float r1 = xk.y + fmaf(uj.x, wp0.y, fmaf(uj.y, wp1.y, fmaf(uj.z, wp2.y, bbv.y)));
                float r2v= xk.z + fmaf(uj.x, wp0.z, fmaf(uj.y, wp1.z, fmaf(uj.z, wp2.z, bbv.z)));
                float r3 = xk.w + fmaf(uj.x, wp0.w, fmaf(uj.y, wp1.w, fmaf(uj.z, wp2.w, bbv.w)));
                float4 h;
                h.x = fmaxf(fmaf(a2.x, r0, c2.x), 0.f);
                h.y = fmaxf(fmaf(a2.y, r1, c2.y), 0.f);
                h.z = fmaxf(fmaf(a2.z, r2v, c2.z), 0.f);
                h.w = fmaxf(fmaf(a2.w, r3, c2.w), 0.f);
                *reinterpret_cast<float4*>(&s_h[warp][r][cb]) = h;
            }
        }
        __syncwarp();
        // phase C: 2 lanes per row; lane&15 = row, lane>>4 = 32-ch chunk
        {
            int rr = lane & 15;
            int chunk = lane >> 4;
            const float4* hp = reinterpret_cast<const float4*>(&s_h[warp][rr][chunk * 32]);
            const float4* wwp = reinterpret_cast<const float4*>(&s_ww1[chunk * 32 * 8]);
            float wk[8];
#pragma unroll
            for (int k = 0; k < 8; k++) wk[k] = (chunk == 0) ? bww1[k] : 0.f;
#pragma unroll
            for (int i = 0; i < 8; i++) {
                float4 v = hp[i];
                {
                    float4 wa = wwp[(4 * i) * 2],     wb = wwp[(4 * i) * 2 + 1];
                    wk[0] = fmaf(v.x, wa.x, wk[0]); wk[1] = fmaf(v.x, wa.y, wk[1]);
                    wk[2] = fmaf(v.x, wa.z, wk[2]); wk[3] = fmaf(v.x, wa.w, wk[3]);
                    wk[4] = fmaf(v.x, wb.x, wk[4]); wk[5] = fmaf(v.x, wb.y, wk[5]);
                    wk[6] = fmaf(v.x, wb.z, wk[6]); wk[7] = fmaf(v.x, wb.w, wk[7]);
                }
                {
                    float4 wa = wwp[(4 * i + 1) * 2], wb = wwp[(4 * i + 1) * 2 + 1];
                    wk[0] = fmaf(v.y, wa.x, wk[0]); wk[1] = fmaf(v.y, wa.y, wk[1]);
                    wk[2] = fmaf(v.y, wa.z, wk[2]); wk[3] = fmaf(v.y, wa.w, wk[3]);
                    wk[4] = fmaf(v.y, wb.x, wk[4]); wk[5] = fmaf(v.y, wb.y, wk[5]);
                    wk[6] = fmaf(v.y, wb.z, wk[6]); wk[7] = fmaf(v.y, wb.w, wk[7]);
                }
                {
                    float4 wa = wwp[(4 * i + 2) * 2], wb = wwp[(4 * i + 2) * 2 + 1];
                    wk[0] = fmaf(v.z, wa.x, wk[0]); wk[1] = fmaf(v.z, wa.y, wk[1]);
                    wk[2] = fmaf(v.z, wa.z, wk[2]); wk[3] = fmaf(v.z, wa.w, wk[3]);
                    wk[4] = fmaf(v.z, wb.x, wk[4]); wk[5] = fmaf(v.z, wb.y, wk[5]);
                    wk[6] = fmaf(v.z, wb.z, wk[6]); wk[7] = fmaf(v.z, wb.w, wk[7]);
                }
                {
                    float4 wa = wwp[(4 * i + 3) * 2], wb = wwp[(4 * i + 3) * 2 + 1];
                    wk[0] = fmaf(v.w, wa.x, wk[0]); wk[1] = fmaf(v.w, wa.y, wk[1]);
                    wk[2] = fmaf(v.w, wa.z, wk[2]); wk[3] = fmaf(v.w, wa.w, wk[3]);
                    wk[4] = fmaf(v.w, wb.x, wk[4]); wk[5] = fmaf(v.w, wb.y, wk[5]);
                    wk[6] = fmaf(v.w, wb.z, wk[6]); wk[7] = fmaf(v.w, wb.w, wk[7]);
                }
            }
#pragma unroll
            for (int k = 0; k < 8; k++)
                wk[k] += __shfl_xor_sync(0xffffffffu, wk[k], 16);
            if (chunk == 0) {
                int row = base + tile * 16 + rr;
                *reinterpret_cast<float4*>(&g_w1[row * 8]) =
                    make_float4(wk[0], wk[1], wk[2], wk[3]);
                *reinterpret_cast<float4*>(&g_w1[row * 8 + 4]) =
                    make_float4(wk[4], wk[5], wk[6], wk[7]);
            }
#pragma unroll
            for (int k = 0; k < 8; k++) {
                float v  = (chunk == 0) ? wk[k] : 0.f;
                float v2 = (chunk == 0) ? wk[k] * wk[k] : 0.f;
#pragma unroll
                for (int o = 16; o; o >>= 1) {
                    v  += __shfl_down_sync(0xffffffffu, v, o);
                    v2 += __shfl_down_sync(0xffffffffu, v2, o);
                }
                if (lane == 0) { atomicAdd(&s_ws[k], v); atomicAdd(&s_wq[k], v2); }
            }
        }
        __syncwarp();
    }
    __syncthreads();
    if (tid < 8) {
        atomicAdd(&g_sum[BN3_OFF + tid], (double)s_ws[tid]);
        atomicAdd(&g_sqs[BN3_OFF + tid], (double)s_wq[tid]);
    }
}

// ---------------- k_p4: bn3 + 8x8 + softmax + weighted sum -> out ----------
__global__ __launch_bounds__(256) void k_p4(
    const int* __restrict__ idx,
    const float* __restrict__ Wp1, const float* __restrict__ bp1,
    const float* __restrict__ Wp2, const float* __restrict__ bp2,
    const float* __restrict__ Ww2, const float* __restrict__ bww2,
    const float* __restrict__ gp, const float* __restrict__ betap,
    const float* __restrict__ gw2, const float* __restrict__ bw2,
    float* __restrict__ out) {
    __shared__ float s_wp2[3][CCH], s_bp2[CCH];
    __shared__ float s_ww2[64];
    __shared__ float s_bww2[8];
    __shared__ __align__(16) float s_w[16][16][8];
    __shared__ __align__(16) float4 s_t1r[16][16];   // {u0,u1,u2, j bits}
    __shared__ float s_a1[4], s_c1[4], s_a3[8], s_c3[8];
    int tid = threadIdx.x;
    bn_to_shared(0, 3, gp, betap, s_a1, s_c1);
    bn_to_shared(BN3_OFF, 8, gw2, bw2, s_a3, s_c3);
    if (tid < CCH) {
        s_wp2[0][tid] = Wp2[tid];
        s_wp2[1][tid] = Wp2[CCH + tid];
        s_wp2[2][tid] = Wp2[2 * CCH + tid];
        s_bp2[tid] = bp2[tid];
        s_ww2[tid] = Ww2[tid];
    }
    if (tid < 8) s_bww2[tid] = bww2[tid];
    __syncthreads();

    int gl = tid & 15;
    int pt = tid >> 4;
    int n = blockIdx.x * 16 + pt;
    int row = n * NSAMP + gl;
    int j = idx[row];

    float4 pj = g_p4[j];
    float4 pn = g_p4[n];
    float dx = pj.x - pn.x, dy = pj.y - pn.y, dz = pj.z - pn.z;
    float t0 = bp1[0] + dx * Wp1[0] + dy * Wp1[3] + dz * Wp1[6];
    float t1 = bp1[1] + dx * Wp1[1] + dy * Wp1[4] + dz * Wp1[7];
    float t2 = bp1[2] + dx * Wp1[2] + dy * Wp1[5] + dz * Wp1[8];
    float u0 = fmaxf(fmaf(s_a1[0], t0, s_c1[0]), 0.f);
    float u1 = fmaxf(fmaf(s_a1[1], t1, s_c1[1]), 0.f);
    float u2 = fmaxf(fmaf(s_a1[2], t2, s_c1[2]), 0.f);
    s_t1r[pt][gl] = make_float4(u0, u1, u2, __int_as_float(j));

    float4 wa = *reinterpret_cast<const float4*>(&g_w1[row * 8]);
    float4 wb = *reinterpret_cast<const float4*>(&g_w1[row * 8 + 4]);
    float v1[8] = {wa.x, wa.y, wa.z, wa.w, wb.x, wb.y, wb.z, wb.w};
    float uu[8];
#pragma unroll
    for (int k = 0; k < 8; k++)
        uu[k] = fmaxf(fmaf(s_a3[k], v1[k], s_c3[k]), 0.f);
    float w2[8];
#pragma unroll
    for (int k2 = 0; k2 < 8; k2++) {
        float acc = s_bww2[k2];
#pragma unroll
        for (int k = 0; k < 8; k++) acc = fmaf(uu[k], s_ww2[k * 8 + k2], acc);
        w2[k2] = acc;
    }
#pragma unroll
    for (int k2 = 0; k2 < 8; k2++) {
        float mx = w2[k2];
        mx = fmaxf(mx, __shfl_xor_sync(0xffffffffu, mx, 1));
        mx = fmaxf(mx, __shfl_xor_sync(0xffffffffu, mx, 2));
        mx = fmaxf(mx, __shfl_xor_sync(0xffffffffu, mx, 4));
        mx = fmaxf(mx, __shfl_xor_sync(0xffffffffu, mx, 8));
        float e = __expf(w2[k2] - mx);
        float s = e;
        s += __shfl_xor_sync(0xffffffffu, s, 1);
        s += __shfl_xor_sync(0xffffffffu, s, 2);
        s += __shfl_xor_sync(0xffffffffu, s, 4);
        s += __shfl_xor_sync(0xffffffffu, s, 8);
        w2[k2] = e / s;
    }
    *reinterpret_cast<float4*>(&s_w[pt][gl][0]) = make_float4(w2[0], w2[1], w2[2], w2[3]);
    *reinterpret_cast<float4*>(&s_w[pt][gl][4]) = make_float4(w2[4], w2[5], w2[6], w2[7]);
    __syncwarp();

    int cb = gl * 4;
    int kb = (gl & 1) * 4;
    float wp0x = s_wp2[0][cb],     wp1x = s_wp2[1][cb],     wp2x = s_wp2[2][cb],     bv0 = s_bp2[cb];
    float wp0y = s_wp2[0][cb + 1], wp1y = s_wp2[1][cb + 1], wp2y = s_wp2[2][cb + 1], bv1 = s_bp2[cb + 1];
    float wp0z = s_wp2[0][cb + 2], wp1z = s_wp2[1][cb + 2], wp2z = s_wp2[2][cb + 2], bv2 = s_bp2[cb + 2];
    float wp0w = s_wp2[0][cb + 3], wp1w = s_wp2[1][cb + 3], wp2w = s_wp2[2][cb + 3], bv3 = s_bp2[cb + 3];
    float o0 = 0.f, o1 = 0.f, o2 = 0.f, o3 = 0.f;
#pragma unroll
    for (int t = 0; t < NSAMP; t++) {
        float4 tj = s_t1r[pt][t];
        int jt = __float_as_int(tj.w);
        float4 xv = ld_half4(&g_xv16[jt * CCH + cb]);
        float4 wt = *reinterpret_cast<const float4*>(&s_w[pt][t][kb]);
        float pr0 = bv0 + tj.x * wp0x + tj.y * wp1x + tj.z * wp2x;
        float pr1 = bv1 + tj.x * wp0y + tj.y * wp1y + tj.z * wp2y;
        float pr2 = bv2 + tj.x * wp0z + tj.y * wp1z + tj.z * wp2z;
        float pr3 = bv3 + tj.x * wp0w + tj.y * wp1w + tj.z * wp2w;
        o0 = fmaf(xv.x + pr0, wt.x, o0);
        o1 = fmaf(xv.y + pr1, wt.y, o1);
        o2 = fmaf(xv.z + pr2, wt.z, o2);
        o3 = fmaf(xv.w + pr3, wt.w, o3);
    }
    *reinterpret_cast<float4*>(&out[n * CCH + cb]) = make_float4(o0, o1, o2, o3);
}

// ---------------- launch ----------------
extern "C" void kernel_launch(void* const* d_in, const int* in_sizes, int n_in,
                              void* d_out, int out_size) {
    const float* p    = (const float*)d_in[0];
    const float* x    = (const float*)d_in[1];
    const int*   idx  = (const int*)  d_in[3];
    const float* Wq   = (const float*)d_in[4];
    const float* bq   = (const float*)d_in[5];
    const float* Wk   = (const float*)d_in[6];
    const float* bk   = (const float*)d_in[7];
    const float* Wv   = (const float*)d_in[8];
    const float* bv   = (const float*)d_in[9];
    const float* Wp1  = (const float*)d_in[10];
    const float* bp1  = (const float*)d_in[11];
    const float* gp   = (const float*)d_in[12];
    const float* betap= (const float*)d_in[13];
    const float* Wp2  = (const float*)d_in[14];
    const float* bp2  = (const float*)d_in[15];
    const float* gw1  = (const float*)d_in[16];
    const float* bw1  = (const float*)d_in[17];
    const float* Ww1  = (const float*)d_in[18];
    const float* bww1 = (const float*)d_in[19];
    const float* gw2  = (const float*)d_in[20];
    const float* bw2  = (const float*)d_in[21];
    const float* Ww2  = (const float*)d_in[22];
    const float* bww2 = (const float*)d_in[23];
    float* out = (float*)d_out;

    k_zero<<<1, 128>>>();                                                    // 0
    k_pad<<<(NPTS + 255) / 256, 256>>>(p);                                   // 1
    k_p1<<<NROW / 256, 256>>>(idx, Wp1, bp1);                                // 2
    k_qkv<<<QKV_GRID, QKV_THREADS>>>(x, Wq, bq, Wk, bk, Wv, bv);             // 3 <- profiled
    k_p2<<<NROW / 256, 256>>>(idx, Wp1, bp1, Wp2, bp2, gp, betap);           // 4
    k_p3<<<NROW / 128, 128>>>(idx, Wp1, bp1, Wp2, bp2, Ww1, bww1,
                              gp, betap, gw1, bw1);                          // 5
    k_p4<<<NPTS / 16, 256>>>(idx, Wp1, bp1, Wp2, bp2, Ww2, bww2,
                             gp, betap, gw2, bw2, out);                      // 6
}

// round 15
// speedup vs baseline: 1.0421x; 1.0421x over previous
#include <cuda_runtime.h>
#include <cuda_fp16.h>

#define NPTS 100000
#define NSAMP 16
#define CCH 64
#define CWCH 8
#define NROW (NPTS * NSAMP)   // 1600000
#define BN_EPS 1e-5f

#define QKV_TILE 16
#define QKV_TILES 5
#define QKV_ROWS (QKV_TILE * QKV_TILES)   // 80
#define QKV_GRID (NPTS / QKV_ROWS)        // 1250
#define QKV_THREADS 192

// raw-stat layout: bn1 at 0..2, bn2 at 4..67, bn3 at 68..75
#define BN2_OFF 4
#define BN3_OFF 68

// ---------------- scratch (__device__ globals: allocation-free, zero-init) ----
__device__ float g_xq[NPTS * CCH];
__device__ __align__(16) __half g_xk16[NPTS * CCH];   // fp16 gather table
__device__ __align__(16) __half g_xv16[NPTS * CCH];   // fp16 gather table
__device__ float g_w1[NROW * CWCH];
__device__ __align__(16) float4 g_p4[NPTS];
__device__ double g_sum[80];
__device__ double g_sqs[80];

// load 4 consecutive fp16 channels -> float4 (one LDG.64)
__device__ __forceinline__ float4 ld_half4(const __half* base) {
    uint2 raw = *reinterpret_cast<const uint2*>(base);
    __half2 h01 = *reinterpret_cast<__half2*>(&raw.x);
    __half2 h23 = *reinterpret_cast<__half2*>(&raw.y);
    float2 f01 = __half22float2(h01);
    float2 f23 = __half22float2(h23);
    return make_float4(f01.x, f01.y, f23.x, f23.y);
}

// per-block BN finalize from raw stats into shared (deterministic, redundant)
__device__ __forceinline__ void bn_to_shared(int off, int nch,
        const float* __restrict__ gamma, const float* __restrict__ beta,
        float* s_a, float* s_c) {
    int i = threadIdx.x;
    if (i < nch) {
        double m = g_sum[off + i] / (double)NROW;
        double v = g_sqs[off + i] / (double)NROW - m * m;
        float a = gamma[i] * rsqrtf((float)v + BN_EPS);
        s_a[i] = a;
        s_c[i] = beta[i] - a * (float)m;
    }
}

// ------ k_pad: p -> g_p4 (float4-padded) + zero stats for this replay -------
__global__ __launch_bounds__(256) void k_pad(const float* __restrict__ p) {
    int i = blockIdx.x * 256 + threadIdx.x;
    if (blockIdx.x == 0 && threadIdx.x < 80) {
        g_sum[threadIdx.x] = 0.0;
        g_sqs[threadIdx.x] = 0.0;
    }
    if (i < NPTS)
        g_p4[i] = make_float4(p[3 * i], p[3 * i + 1], p[3 * i + 2], 0.f);
}

// ---- k_qkv: [N,64]x[64,192] GEMM (weights in registers) + fused bn1 stats ----
// 3 blocks/SM via launch_bounds; grid 1250 for balance.
__global__ __launch_bounds__(QKV_THREADS, 3) void k_qkv(
    const float* __restrict__ x, const int* __restrict__ idx,
    const float* __restrict__ Wq, const float* __restrict__ bq,
    const float* __restrict__ Wk, const float* __restrict__ bk,
    const float* __restrict__ Wv, const float* __restrict__ bv,
    const float* __restrict__ Wp1, const float* __restrict__ bp1) {
    __shared__ __align__(16) float xs[QKV_TILE][CCH];
    __shared__ float ss[3], sq[3];
    int c = threadIdx.x;             // 0..191
    if (c < 3) { ss[c] = 0.f; sq[c] = 0.f; }

    const float* W; const float* b; int cc; int sect;
    if (c < 64)       { W = Wq; b = bq; cc = c;       sect = 0; }
    else if (c < 128) { W = Wk; b = bk; cc = c - 64;  sect = 1; }
    else              { W = Wv; b = bv; cc = c - 128; sect = 2; }

    float w[CCH];
#pragma unroll
    for (int j = 0; j < CCH; j++) w[j] = W[j * CCH + cc];
    float bb = b[cc];

    int rb0 = blockIdx.x * QKV_ROWS;
    for (int t = 0; t < QKV_TILES; t++) {
        int rb = rb0 + t * QKV_TILE;
        __syncthreads();
        for (int i = c; i < QKV_TILE * CCH / 4; i += QKV_THREADS) {
            int r = i >> 4, c4 = i & 15;
            *reinterpret_cast<float4*>(&xs[r][c4 * 4]) =
                *reinterpret_cast<const float4*>(&x[(rb + r) * CCH + c4 * 4]);
        }
        __syncthreads();

        float acc[QKV_TILE];
#pragma unroll
        for (int r = 0; r < QKV_TILE; r++) acc[r] = bb;
#pragma unroll
        for (int j4 = 0; j4 < 16; j4++) {
            float w0 = w[4 * j4], w1 = w[4 * j4 + 1], w2 = w[4 * j4 + 2], w3 = w[4 * j4 + 3];
#pragma unroll
            for (int r = 0; r < QKV_TILE; r++) {
                float4 xv = *reinterpret_cast<const float4*>(&xs[r][4 * j4]);
                acc[r] = fmaf(w0, xv.x, acc[r]);
                acc[r] = fmaf(w1, xv.y, acc[r]);
                acc[r] = fmaf(w2, xv.z, acc[r]);
                acc[r] = fmaf(w3, xv.w, acc[r]);
            }
        }
        if (sect == 0) {
#pragma unroll
            for (int r = 0; r < QKV_TILE; r++)
                g_xq[(rb + r) * CCH + cc] = acc[r];
        } else if (sect == 1) {
#pragma unroll
            for (int r = 0; r < QKV_TILE; r++)
                g_xk16[(rb + r) * CCH + cc] = __float2half_rn(acc[r]);
        } else {
#pragma unroll
            for (int r = 0; r < QKV_TILE; r++)
                g_xv16[(rb + r) * CCH + cc] = __float2half_rn(acc[r]);
        }
    }

    // ---- fused bn1 stats over t1 = p_r0 @ Wp1 + bp1 (grid-stride) ----
    float w00 = Wp1[0], w01 = Wp1[1], w02 = Wp1[2];
    float w10 = Wp1[3], w11 = Wp1[4], w12 = Wp1[5];
    float w20 = Wp1[6], w21 = Wp1[7], w22 = Wp1[8];
    float b0 = bp1[0], b1 = bp1[1], b2 = bp1[2];
    float a0 = 0.f, a1 = 0.f, a2 = 0.f, q0 = 0.f, q1 = 0.f, q2 = 0.f;
    for (int row = blockIdx.x * QKV_THREADS + c; row < NROW;
         row += QKV_GRID * QKV_THREADS) {
        int j = idx[row];
        float4 pj = g_p4[j];
        float4 pn = g_p4[row >> 4];
        float dx = pj.x - pn.x, dy = pj.y - pn.y, dz = pj.z - pn.z;
        float t0 = b0 + dx * w00 + dy * w10 + dz * w20;
        float t1 = b1 + dx * w01 + dy * w11 + dz * w21;
        float t2 = b2 + dx * w02 + dy * w12 + dz * w22;
        a0 += t0; q0 = fmaf(t0, t0, q0);
        a1 += t1; q1 = fmaf(t1, t1, q1);
        a2 += t2; q2 = fmaf(t2, t2, q2);
    }
#pragma unroll
    for (int o = 16; o; o >>= 1) {
        a0 += __shfl_down_sync(0xffffffffu, a0, o);
        a1 += __shfl_down_sync(0xffffffffu, a1, o);
        a2 += __shfl_down_sync(0xffffffffu, a2, o);
        q0 += __shfl_down_sync(0xffffffffu, q0, o);
        q1 += __shfl_down_sync(0xffffffffu, q1, o);
        q2 += __shfl_down_sync(0xffffffffu, q2, o);
    }
    if ((c & 31) == 0) {
        atomicAdd(&ss[0], a0); atomicAdd(&sq[0], q0);
        atomicAdd(&ss[1], a1); atomicAdd(&sq[1], q1);
        atomicAdd(&ss[2], a2); atomicAdd(&sq[2], q2);
    }
    __syncthreads();
    if (c < 3) {
        atomicAdd(&g_sum[c], (double)ss[c]);
        atomicAdd(&g_sqs[c], (double)sq[c]);
    }
}

// ---------------- k_p2: bn2 stats over r_qk (fp16 xk gathers) ----------------
__global__ __launch_bounds__(256) void k_p2(
    const int* __restrict__ idx,
    const float* __restrict__ Wp1, const float* __restrict__ bp1,
    const float* __restrict__ Wp2, const float* __restrict__ bp2,
    const float* __restrict__ gp, const float* __restrict__ betap) {
    __shared__ __align__(16) float s_wp2[3][CCH];
    __shared__ __align__(16) float s_bp2[CCH];
    __shared__ float s_sum[CCH], s_sq[CCH];
    __shared__ __align__(16) float4 s_uj[8][32];
    __shared__ float s_a1[4], s_c1[4];
    int tid = threadIdx.x;
    bn_to_shared(0, 3, gp, betap, s_a1, s_c1);
    if (tid < CCH) {
        s_wp2[0][tid] = Wp2[tid];
        s_wp2[1][tid] = Wp2[CCH + tid];
        s_wp2[2][tid] = Wp2[2 * CCH + tid];
        s_bp2[tid] = bp2[tid];
        s_sum[tid] = 0.f; s_sq[tid] = 0.f;
    }
    float w00 = Wp1[0], w01 = Wp1[1], w02 = Wp1[2];
    float w10 = Wp1[3], w11 = Wp1[4], w12 = Wp1[5];
    float w20 = Wp1[6], w21 = Wp1[7], w22 = Wp1[8];
    float b0 = bp1[0], b1 = bp1[1], b2 = bp1[2];
    __syncthreads();
    int warp = tid >> 5, lane = tid & 31;
    int base = blockIdx.x * 256 + warp * 32;   // 32 rows = 2 points
    // phase A: own row -> u, j in smem
    {
        int row = base + lane;
        int j_own = idx[row];
        float4 pj = g_p4[j_own];
        float4 pn = g_p4[row >> 4];
        float dx = pj.x - pn.x, dy = pj.y - pn.y, dz = pj.z - pn.z;
        float t0 = b0 + dx * w00 + dy * w10 + dz * w20;
        float t1 = b1 + dx * w01 + dy * w11 + dz * w21;
        float t2 = b2 + dx * w02 + dy * w12 + dz * w22;
        float u0 = fmaxf(fmaf(s_a1[0], t0, s_c1[0]), 0.f);
        float u1 = fmaxf(fmaf(s_a1[1], t1, s_c1[1]), 0.f);
        float u2 = fmaxf(fmaf(s_a1[2], t2, s_c1[2]), 0.f);
        s_uj[warp][lane] = make_float4(u0, u1, u2, __int_as_float(j_own));
    }
    __syncwarp();
    // phase B: half-warp per point; lane owns channels cb..cb+3 (LDG.64 fp16)
    int half = lane >> 4;
    int cb = (lane & 15) * 4;
    int n0 = (base >> 4) + half;
    float4 wp0 = *reinterpret_cast<const float4*>(&s_wp2[0][cb]);
    float4 wp1 = *reinterpret_cast<const float4*>(&s_wp2[1][cb]);
    float4 wp2 = *reinterpret_cast<const float4*>(&s_wp2[2][cb]);
    float4 bbv = *reinterpret_cast<const float4*>(&s_bp2[cb]);
    {
        float4 qv = *reinterpret_cast<const float4*>(&g_xq[n0 * CCH + cb]);
        bbv.x -= qv.x; bbv.y -= qv.y; bbv.z -= qv.z; bbv.w -= qv.w;
    }
    float4 sum = make_float4(0.f, 0.f, 0.f, 0.f);
    float4 sq  = make_float4(0.f, 0.f, 0.f, 0.f);
#pragma unroll
    for (int r2 = 0; r2 < 16; r2++) {
        float4 uj = s_uj[warp][half * 16 + r2];
        int jr = __float_as_int(uj.w);
        float4 xk = ld_half4(&g_xk16[jr * CCH + cb]);
        float r0 = xk.x + fmaf(uj.x, wp0.x, fmaf(uj.y, wp1.x, fmaf(uj.z, wp2.x, bbv.x)));
        float r1 = xk.y + fmaf(uj.x, wp0.y, fmaf(uj.y, wp1.y, fmaf(uj.z, wp2.y, bbv.y)));
        float r2v= xk.z + fmaf(uj.x, wp0.z, fmaf(uj.y, wp1.z, fmaf(uj.z, wp2.z, bbv.z)));
        float r3 = xk.w + fmaf(uj.x, wp0.w, fmaf(uj.y, wp1.w, fmaf(uj.z, wp2.w, bbv.w)));
        sum.x += r0;  sq.x = fmaf(r0, r0, sq.x);
        sum.y += r1;  sq.y = fmaf(r1, r1, sq.y);
        sum.z += r2v; sq.z = fmaf(r2v, r2v, sq.z);
        sum.w += r3;  sq.w = fmaf(r3, r3, sq.w);
    }
    atomicAdd(&s_sum[cb],     sum.x); atomicAdd(&s_sq[cb],     sq.x);
    atomicAdd(&s_sum[cb + 1], sum.y); atomicAdd(&s_sq[cb + 1], sq.y);
    atomicAdd(&s_sum[cb + 2], sum.z); atomicAdd(&s_sq[cb + 2], sq.z);
    atomicAdd(&s_sum[cb + 3], sum.w); atomicAdd(&s_sq[cb + 3], sq.w);
    __syncthreads();
    if (tid < CCH) {
        atomicAdd(&g_sum[BN2_OFF + tid], (double)s_sum[tid]);
        atomicAdd(&g_sqs[BN2_OFF + tid], (double)s_sq[tid]);
    }
}

// ------- k_p3: w1 = relu(bn2(r_qk)) @ Ww1 + bww1, store + bn3 stats ---------
__global__ __launch_bounds__(128, 8) void k_p3(
    const int* __restrict__ idx,
    const float* __restrict__ Wp1, const float* __restrict__ bp1,
    const float* __restrict__ Wp2, const float* __restrict__ bp2,
    const float* __restrict__ Ww1, const float* __restrict__ bww1,
    const float* __restrict__ gp, const float* __restrict__ betap,
    const float* __restrict__ gw1, const float* __restrict__ bw1) {
    __shared__ __align__(16) float s_h[4][16][68];
    __shared__ __align__(16) float s_ww1[CCH * CWCH];
    __shared__ __align__(16) float s_wp2[3][CCH];
    __shared__ __align__(16) float s_bp2[CCH];
    __shared__ float s_ws[8], s_wq[8];
    __shared__ __align__(16) float4 s_uj[4][32];
    __shared__ float s_a1[4], s_c1[4];
    __shared__ __align__(16) float s_a2[CCH];
    __shared__ __align__(16) float s_c2[CCH];
    int tid = threadIdx.x;
    bn_to_shared(0, 3, gp, betap, s_a1, s_c1);
    bn_to_shared(BN2_OFF, CCH, gw1, bw1, s_a2, s_c2);
    for (int i = tid; i < CCH * CWCH; i += 128) s_ww1[i] = Ww1[i];
    if (tid < CCH) {
        s_wp2[0][tid] = Wp2[tid];
        s_wp2[1][tid] = Wp2[CCH + tid];
        s_wp2[2][tid] = Wp2[2 * CCH + tid];
        s_bp2[tid] = bp2[tid];
    }
    if (tid < 8) { s_ws[tid] = 0.f; s_wq[tid] = 0.f; }
    __syncthreads();
    int warp = tid >> 5, lane = tid & 31;
    int base = blockIdx.x * 128 + warp * 32;
    // phase A: all 32 rows of this warp
    {
        int row = base + lane;
        int j_own = idx[row];
        float4 pj = g_p4[j_own];
        float4 pn = g_p4[row >> 4];
        float dx = pj.x - pn.x, dy = pj.y - pn.y, dz = pj.z - pn.z;
        float t0 = bp1[0] + dx * Wp1[0] + dy * Wp1[3] + dz * Wp1[6];
        float t1 = bp1[1] + dx * Wp1[1] + dy * Wp1[4] + dz * Wp1[7];
        float t2 = bp1[2] + dx * Wp1[2] + dy * Wp1[5] + dz * Wp1[8];
        float u0 = fmaxf(fmaf(s_a1[0], t0, s_c1[0]), 0.f);
        float u1 = fmaxf(fmaf(s_a1[1], t1, s_c1[1]), 0.f);
        float u2 = fmaxf(fmaf(s_a1[2], t2, s_c1[2]), 0.f);
        s_uj[warp][lane] = make_float4(u0, u1, u2, __int_as_float(j_own));
    }
    __syncwarp();

#pragma unroll
    for (int tile = 0; tile < 2; tile++) {
        // phase B: one point (16 rows); half-warp covers 8 rows; lane owns 4 ch
        {
            int half = lane >> 4;
            int cb = (lane & 15) * 4;
            int nt = (base >> 4) + tile;
            float4 a2 = *reinterpret_cast<const float4*>(&s_a2[cb]);
            float4 c2 = *reinterpret_cast<const float4*>(&s_c2[cb]);
            float4 wp0 = *reinterpret_cast<const float4*>(&s_wp2[0][cb]);
            float4 wp1 = *reinterpret_cast<const float4*>(&s_wp2[1][cb]);
            float4 wp2 = *reinterpret_cast<const float4*>(&s_wp2[2][cb]);
            float4 bbv = *reinterpret_cast<const float4*>(&s_bp2[cb]);
            {
                float4 qv = *reinterpret_cast<const float4*>(&g_xq[nt * CCH + cb]);
                bbv.x -= qv.x; bbv.y -= qv.y; bbv.z -= qv.z; bbv.w -= qv.w;
            }
#pragma unroll
            for (int r2 = 0; r2 < 8; r2++) {
                int r = half * 8 + r2;
                float4 uj = s_uj[warp][tile * 16 + r];
                int jr = __float_as_int(uj.w);
                float4 xk = ld_half4(&g_xk16[jr * CCH + cb]);
                float r0 = xk.x + fmaf(uj.x, wp0.x, fmaf(uj.y, wp1.x, fmaf(uj.z, wp2.x, bbv.x)));
                float r1 = xk.y + fmaf(uj.x, wp0.y, fmaf(uj.y, wp1.y, fmaf(uj.z, wp2.y, bbv.y)));
                float r2v= xk.z + fmaf(uj.x, wp0.z, fmaf(uj.y, wp1.z, fmaf(uj.z, wp2.z, bbv.z)));
                float r3 = xk.w + fmaf(uj.x, wp0.w, fmaf(uj.y, wp1.w, fmaf(uj.z, wp2.w, bbv.w)));
                float4 h;
                h.x = fmaxf(fmaf(a2.x, r0, c2.x), 0.f);
                h.y = fmaxf(fmaf(a2.y, r1, c2.y), 0.f);
                h.z = fmaxf(fmaf(a2.z, r2v, c2.z), 0.f);
                h.w = fmaxf(fmaf(a2.w, r3, c2.w), 0.f);
                *reinterpret_cast<float4*>(&s_h[warp][r][cb]) = h;
            }
        }
        __syncwarp();
        // phase C: 2 lanes per row; lane&15 = row, lane>>4 = 32-ch chunk
        {
            int rr = lane & 15;
            int chunk = lane >> 4;
            const float4* hp = reinterpret_cast<const float4*>(&s_h[warp][rr][chunk * 32]);
            const float4* wwp = reinterpret_cast<const float4*>(&s_ww1[chunk * 32 * 8]);
            float wk[8];
#pragma unroll
            for (int k = 0; k < 8; k++) wk[k] = (chunk == 0) ? bww1[k] : 0.f;
#pragma unroll
            for (int i = 0; i < 8; i++) {
                float4 v = hp[i];
                {
                    float4 wa = wwp[(4 * i) * 2],     wb = wwp[(4 * i) * 2 + 1];
                    wk[0] = fmaf(v.x, wa.x, wk[0]); wk[1] = fmaf(v.x, wa.y, wk[1]);
                    wk[2] = fmaf(v.x, wa.z, wk[2]); wk[3] = fmaf(v.x, wa.w, wk[3]);
                    wk[4] = fmaf(v.x, wb.x, wk[4]); wk[5] = fmaf(v.x, wb.y, wk[5]);
                    wk[6] = fmaf(v.x, wb.z, wk[6]); wk[7] = fmaf(v.x, wb.w, wk[7]);
                }
                {
                    float4 wa = wwp[(4 * i + 1) * 2], wb = wwp[(4 * i + 1) * 2 + 1];
                    wk[0] = fmaf(v.y, wa.x, wk[0]); wk[1] = fmaf(v.y, wa.y, wk[1]);
                    wk[2] = fmaf(v.y, wa.z, wk[2]); wk[3] = fmaf(v.y, wa.w, wk[3]);
                    wk[4] = fmaf(v.y, wb.x, wk[4]); wk[5] = fmaf(v.y, wb.y, wk[5]);
                    wk[6] = fmaf(v.y, wb.z, wk[6]); wk[7] = fmaf(v.y, wb.w, wk[7]);
                }
                {
                    float4 wa = wwp[(4 * i + 2) * 2], wb = wwp[(4 * i + 2) * 2 + 1];
                    wk[0] = fmaf(v.z, wa.x, wk[0]); wk[1] = fmaf(v.z, wa.y, wk[1]);
                    wk[2] = fmaf(v.z, wa.z, wk[2]); wk[3] = fmaf(v.z, wa.w, wk[3]);
                    wk[4] = fmaf(v.z, wb.x, wk[4]); wk[5] = fmaf(v.z, wb.y, wk[5]);
                    wk[6] = fmaf(v.z, wb.z, wk[6]); wk[7] = fmaf(v.z, wb.w, wk[7]);
                }
                {
                    float4 wa = wwp[(4 * i + 3) * 2], wb = wwp[(4 * i + 3) * 2 + 1];
                    wk[0] = fmaf(v.w, wa.x, wk[0]); wk[1] = fmaf(v.w, wa.y, wk[1]);
                    wk[2] = fmaf(v.w, wa.z, wk[2]); wk[3] = fmaf(v.w, wa.w, wk[3]);
                    wk[4] = fmaf(v.w, wb.x, wk[4]); wk[5] = fmaf(v.w, wb.y, wk[5]);
                    wk[6] = fmaf(v.w, wb.z, wk[6]); wk[7] = fmaf(v.w, wb.w, wk[7]);
                }
            }
#pragma unroll
            for (int k = 0; k < 8; k++)
                wk[k] += __shfl_xor_sync(0xffffffffu, wk[k], 16);
            if (chunk == 0) {
                int row = base + tile * 16 + rr;
                *reinterpret_cast<float4*>(&g_w1[row * 8]) =
                    make_float4(wk[0], wk[1], wk[2], wk[3]);
                *reinterpret_cast<float4*>(&g_w1[row * 8 + 4]) =
                    make_float4(wk[4], wk[5], wk[6], wk[7]);
            }
#pragma unroll
            for (int k = 0; k < 8; k++) {
                float v  = (chunk == 0) ? wk[k] : 0.f;
                float v2 = (chunk == 0) ? wk[k] * wk[k] : 0.f;
#pragma unroll
                for (int o = 16; o; o >>= 1) {
                    v  += __shfl_down_sync(0xffffffffu, v, o);
                    v2 += __shfl_down_sync(0xffffffffu, v2, o);
                }
                if (lane == 0) { atomicAdd(&s_ws[k], v); atomicAdd(&s_wq[k], v2); }
            }
        }
        __syncwarp();
    }
    __syncthreads();
    if (tid < 8) {
        atomicAdd(&g_sum[BN3_OFF + tid], (double)s_ws[tid]);
        atomicAdd(&g_sqs[BN3_OFF + tid], (double)s_wq[tid]);
    }
}

// ---------------- k_p4: bn3 + 8x8 + softmax + weighted sum -> out ----------
__global__ __launch_bounds__(256) void k_p4(
    const int* __restrict__ idx,
    const float* __restrict__ Wp1, const float* __restrict__ bp1,
    const float* __restrict__ Wp2, const float* __restrict__ bp2,
    const float* __restrict__ Ww2, const float* __restrict__ bww2,
    const float* __restrict__ gp, const float* __restrict__ betap,
    const float* __restrict__ gw2, const float* __restrict__ bw2,
    float* __restrict__ out) {
    __shared__ float s_wp2[3][CCH], s_bp2[CCH];
    __shared__ float s_ww2[64];
    __shared__ float s_bww2[8];
    __shared__ __align__(16) float s_w[16][16][8];
    __shared__ __align__(16) float4 s_t1r[16][16];   // {u0,u1,u2, j bits}
    __shared__ float s_a1[4], s_c1[4], s_a3[8], s_c3[8];
    int tid = threadIdx.x;
    bn_to_shared(0, 3, gp, betap, s_a1, s_c1);
    bn_to_shared(BN3_OFF, 8, gw2, bw2, s_a3, s_c3);
    if (tid < CCH) {
        s_wp2[0][tid] = Wp2[tid];
        s_wp2[1][tid] = Wp2[CCH + tid];
        s_wp2[2][tid] = Wp2[2 * CCH + tid];
        s_bp2[tid] = bp2[tid];
        s_ww2[tid] = Ww2[tid];
    }
    if (tid < 8) s_bww2[tid] = bww2[tid];
    __syncthreads();

    int gl = tid & 15;
    int pt = tid >> 4;
    int n = blockIdx.x * 16 + pt;
    int row = n * NSAMP + gl;
    int j = idx[row];

    float4 pj = g_p4[j];
    float4 pn = g_p4[n];
    float dx = pj.x - pn.x, dy = pj.y - pn.y, dz = pj.z - pn.z;
    float t0 = bp1[0] + dx * Wp1[0] + dy * Wp1[3] + dz * Wp1[6];
    float t1 = bp1[1] + dx * Wp1[1] + dy * Wp1[4] + dz * Wp1[7];
    float t2 = bp1[2] + dx * Wp1[2] + dy * Wp1[5] + dz * Wp1[8];
    float u0 = fmaxf(fmaf(s_a1[0], t0, s_c1[0]), 0.f);
    float u1 = fmaxf(fmaf(s_a1[1], t1, s_c1[1]), 0.f);
    float u2 = fmaxf(fmaf(s_a1[2], t2, s_c1[2]), 0.f);
    s_t1r[pt][gl] = make_float4(u0, u1, u2, __int_as_float(j));

    float4 wa = *reinterpret_cast<const float4*>(&g_w1[row * 8]);
    float4 wb = *reinterpret_cast<const float4*>(&g_w1[row * 8 + 4]);
    float v1[8] = {wa.x, wa.y, wa.z, wa.w, wb.x, wb.y, wb.z, wb.w};
    float uu[8];
#pragma unroll
    for (int k = 0; k < 8; k++)
        uu[k] = fmaxf(fmaf(s_a3[k], v1[k], s_c3[k]), 0.f);
    float w2[8];
#pragma unroll
    for (int k2 = 0; k2 < 8; k2++) {
        float acc = s_bww2[k2];
#pragma unroll
        for (int k = 0; k < 8; k++) acc = fmaf(uu[k], s_ww2[k * 8 + k2], acc);
        w2[k2] = acc;
    }
#pragma unroll
    for (int k2 = 0; k2 < 8; k2++) {
        float mx = w2[k2];
        mx = fmaxf(mx, __shfl_xor_sync(0xffffffffu, mx, 1));
        mx = fmaxf(mx, __shfl_xor_sync(0xffffffffu, mx, 2));
        mx = fmaxf(mx, __shfl_xor_sync(0xffffffffu, mx, 4));
        mx = fmaxf(mx, __shfl_xor_sync(0xffffffffu, mx, 8));
        float e = __expf(w2[k2] - mx);
        float s = e;
        s += __shfl_xor_sync(0xffffffffu, s, 1);
        s += __shfl_xor_sync(0xffffffffu, s, 2);
        s += __shfl_xor_sync(0xffffffffu, s, 4);
        s += __shfl_xor_sync(0xffffffffu, s, 8);
        w2[k2] = e / s;
    }
    *reinterpret_cast<float4*>(&s_w[pt][gl][0]) = make_float4(w2[0], w2[1], w2[2], w2[3]);
    *reinterpret_cast<float4*>(&s_w[pt][gl][4]) = make_float4(w2[4], w2[5], w2[6], w2[7]);
    __syncwarp();

    int cb = gl * 4;
    int kb = (gl & 1) * 4;
    float wp0x = s_wp2[0][cb],     wp1x = s_wp2[1][cb],     wp2x = s_wp2[2][cb],     bv0 = s_bp2[cb];
    float wp0y = s_wp2[0][cb + 1], wp1y = s_wp2[1][cb + 1], wp2y = s_wp2[2][cb + 1], bv1 = s_bp2[cb + 1];
    float wp0z = s_wp2[0][cb + 2], wp1z = s_wp2[1][cb + 2], wp2z = s_wp2[2][cb + 2], bv2 = s_bp2[cb + 2];
    float wp0w = s_wp2[0][cb + 3], wp1w = s_wp2[1][cb + 3], wp2w = s_wp2[2][cb + 3], bv3 = s_bp2[cb + 3];
    float o0 = 0.f, o1 = 0.f, o2 = 0.f, o3 = 0.f;
#pragma unroll
    for (int t = 0; t < NSAMP; t++) {
        float4 tj = s_t1r[pt][t];
        int jt = __float_as_int(tj.w);
        float4 xv = ld_half4(&g_xv16[jt * CCH + cb]);
        float4 wt = *reinterpret_cast<const float4*>(&s_w[pt][t][kb]);
        float pr0 = bv0 + tj.x * wp0x + tj.y * wp1x + tj.z * wp2x;
        float pr1 = bv1 + tj.x * wp0y + tj.y * wp1y + tj.z * wp2y;
        float pr2 = bv2 + tj.x * wp0z + tj.y * wp1z + tj.z * wp2z;
        float pr3 = bv3 + tj.x * wp0w + tj.y * wp1w + tj.z * wp2w;
        o0 = fmaf(xv.x + pr0, wt.x, o0);
        o1 = fmaf(xv.y + pr1, wt.y, o1);
        o2 = fmaf(xv.z + pr2, wt.z, o2);
        o3 = fmaf(xv.w + pr3, wt.w, o3);
    }
    *reinterpret_cast<float4*>(&out[n * CCH + cb]) = make_float4(o0, o1, o2, o3);
}

// ---------------- launch ----------------
extern "C" void kernel_launch(void* const* d_in, const int* in_sizes, int n_in,
                              void* d_out, int out_size) {
    const float* p    = (const float*)d_in[0];
    const float* x    = (const float*)d_in[1];
    const int*   idx  = (const int*)  d_in[3];
    const float* Wq   = (const float*)d_in[4];
    const float* bq   = (const float*)d_in[5];
    const float* Wk   = (const float*)d_in[6];
    const float* bk   = (const float*)d_in[7];
    const float* Wv   = (const float*)d_in[8];
    const float* bv   = (const float*)d_in[9];
    const float* Wp1  = (const float*)d_in[10];
    const float* bp1  = (const float*)d_in[11];
    const float* gp   = (const float*)d_in[12];
    const float* betap= (const float*)d_in[13];
    const float* Wp2  = (const float*)d_in[14];
    const float* bp2  = (const float*)d_in[15];
    const float* gw1  = (const float*)d_in[16];
    const float* bw1  = (const float*)d_in[17];
    const float* Ww1  = (const float*)d_in[18];
    const float* bww1 = (const float*)d_in[19];
    const float* gw2  = (const float*)d_in[20];
    const float* bw2  = (const float*)d_in[21];
    const float* Ww2  = (const float*)d_in[22];
    const float* bww2 = (const float*)d_in[23];
    float* out = (float*)d_out;

    k_pad<<<(NPTS + 255) / 256, 256>>>(p);                                   // 0
    k_qkv<<<QKV_GRID, QKV_THREADS>>>(x, idx, Wq, bq, Wk, bk, Wv, bv,
                                     Wp1, bp1);                              // 1
    k_p2<<<NROW / 256, 256>>>(idx, Wp1, bp1, Wp2, bp2, gp, betap);           // 2
    k_p3<<<NROW / 128, 128>>>(idx, Wp1, bp1, Wp2, bp2, Ww1, bww1,
                              gp, betap, gw1, bw1);                          // 3 <- profiled
    k_p4<<<NPTS / 16, 256>>>(idx, Wp1, bp1, Wp2, bp2, Ww2, bww2,
                             gp, betap, gw2, bw2, out);                      // 4
}

// round 17
// speedup vs baseline: 1.2892x; 1.2371x over previous
#include <cuda_runtime.h>
#include <cuda_fp16.h>
#include <cstdint>

#define NPTS 100000
#define NSAMP 16
#define CCH 64
#define CWCH 8
#define NROW (NPTS * NSAMP)   // 1600000
#define BN_EPS 1e-5f

#define QKV_TILE 16
#define QKV_TILES 5
#define QKV_ROWS (QKV_TILE * QKV_TILES)   // 80
#define QKV_GRID (NPTS / QKV_ROWS)        // 1250
#define QKV_THREADS 192

// raw-stat layout: bn1 at 0..2, bn2 at 4..67, bn3 at 68..75
#define BN2_OFF 4
#define BN3_OFF 68

// ---------------- scratch (__device__ globals: allocation-free, zero-init) ----
__device__ float g_xq[NPTS * CCH];
__device__ __align__(16) __half g_xk16[NPTS * CCH];   // fp16 gather table
__device__ __align__(16) __half g_xv16[NPTS * CCH];   // fp16 gather table
__device__ float g_w1[NROW * CWCH];
__device__ __align__(16) float4 g_p4[NPTS];
__device__ double g_sum[80];
__device__ double g_sqs[80];

// load 4 consecutive fp16 channels -> float4 (one LDG.64)
__device__ __forceinline__ float4 ld_half4(const __half* base) {
    uint2 raw = *reinterpret_cast<const uint2*>(base);
    __half2 h01 = *reinterpret_cast<__half2*>(&raw.x);
    __half2 h23 = *reinterpret_cast<__half2*>(&raw.y);
    float2 f01 = __half22float2(h01);
    float2 f23 = __half22float2(h23);
    return make_float4(f01.x, f01.y, f23.x, f23.y);
}

// per-block BN finalize from raw stats into shared (deterministic, redundant)
__device__ __forceinline__ void bn_to_shared(int off, int nch,
        const float* __restrict__ gamma, const float* __restrict__ beta,
        float* s_a, float* s_c) {
    int i = threadIdx.x;
    if (i < nch) {
        double m = g_sum[off + i] / (double)NROW;
        double v = g_sqs[off + i] / (double)NROW - m * m;
        float a = gamma[i] * rsqrtf((float)v + BN_EPS);
        s_a[i] = a;
        s_c[i] = beta[i] - a * (float)m;
    }
}

// ------ k_pad: p -> g_p4 (float4-padded) + zero stats for this replay -------
__global__ __launch_bounds__(256) void k_pad(const float* __restrict__ p) {
    int i = blockIdx.x * 256 + threadIdx.x;
    if (blockIdx.x == 0 && threadIdx.x < 80) {
        g_sum[threadIdx.x] = 0.0;
        g_sqs[threadIdx.x] = 0.0;
    }
    if (i < NPTS)
        g_p4[i] = make_float4(p[3 * i], p[3 * i + 1], p[3 * i + 2], 0.f);
}

// ---- k_qkv: [N,64]x[64,192] GEMM (weights in registers) + fused bn1 stats ----
__global__ __launch_bounds__(QKV_THREADS, 3) void k_qkv(
    const float* __restrict__ x, const int* __restrict__ idx,
    const float* __restrict__ Wq, const float* __restrict__ bq,
    const float* __restrict__ Wk, const float* __restrict__ bk,
    const float* __restrict__ Wv, const float* __restrict__ bv,
    const float* __restrict__ Wp1, const float* __restrict__ bp1) {
    __shared__ __align__(16) float xs[QKV_TILE][CCH];
    __shared__ float ss[3], sq[3];
    int c = threadIdx.x;             // 0..191
    if (c < 3) { ss[c] = 0.f; sq[c] = 0.f; }

    const float* W; const float* b; int cc; int sect;
    if (c < 64)       { W = Wq; b = bq; cc = c;       sect = 0; }
    else if (c < 128) { W = Wk; b = bk; cc = c - 64;  sect = 1; }
    else              { W = Wv; b = bv; cc = c - 128; sect = 2; }

    float w[CCH];
#pragma unroll
    for (int j = 0; j < CCH; j++) w[j] = W[j * CCH + cc];
    float bb = b[cc];

    int rb0 = blockIdx.x * QKV_ROWS;
    for (int t = 0; t < QKV_TILES; t++) {
        int rb = rb0 + t * QKV_TILE;
        __syncthreads();
        for (int i = c; i < QKV_TILE * CCH / 4; i += QKV_THREADS) {
            int r = i >> 4, c4 = i & 15;
            *reinterpret_cast<float4*>(&xs[r][c4 * 4]) =
                *reinterpret_cast<const float4*>(&x[(rb + r) * CCH + c4 * 4]);
        }
        __syncthreads();

        float acc[QKV_TILE];
#pragma unroll
        for (int r = 0; r < QKV_TILE; r++) acc[r] = bb;
#pragma unroll
        for (int j4 = 0; j4 < 16; j4++) {
            float w0 = w[4 * j4], w1 = w[4 * j4 + 1], w2 = w[4 * j4 + 2], w3 = w[4 * j4 + 3];
#pragma unroll
            for (int r = 0; r < QKV_TILE; r++) {
                float4 xv = *reinterpret_cast<const float4*>(&xs[r][4 * j4]);
                acc[r] = fmaf(w0, xv.x, acc[r]);
                acc[r] = fmaf(w1, xv.y, acc[r]);
                acc[r] = fmaf(w2, xv.z, acc[r]);
                acc[r] = fmaf(w3, xv.w, acc[r]);
            }
        }
        if (sect == 0) {
#pragma unroll
            for (int r = 0; r < QKV_TILE; r++)
                g_xq[(rb + r) * CCH + cc] = acc[r];
        } else if (sect == 1) {
#pragma unroll
            for (int r = 0; r < QKV_TILE; r++)
                g_xk16[(rb + r) * CCH + cc] = __float2half_rn(acc[r]);
        } else {
#pragma unroll
            for (int r = 0; r < QKV_TILE; r++)
                g_xv16[(rb + r) * CCH + cc] = __float2half_rn(acc[r]);
        }
    }

    // ---- fused bn1 stats over t1 = p_r0 @ Wp1 + bp1 (grid-stride) ----
    float w00 = Wp1[0], w01 = Wp1[1], w02 = Wp1[2];
    float w10 = Wp1[3], w11 = Wp1[4], w12 = Wp1[5];
    float w20 = Wp1[6], w21 = Wp1[7], w22 = Wp1[8];
    float b0 = bp1[0], b1 = bp1[1], b2 = bp1[2];
    float a0 = 0.f, a1 = 0.f, a2 = 0.f, q0 = 0.f, q1 = 0.f, q2 = 0.f;
    for (int row = blockIdx.x * QKV_THREADS + c; row < NROW;
         row += QKV_GRID * QKV_THREADS) {
        int j = idx[row];
        float4 pj = g_p4[j];
        float4 pn = g_p4[row >> 4];
        float dx = pj.x - pn.x, dy = pj.y - pn.y, dz = pj.z - pn.z;
        float t0 = b0 + dx * w00 + dy * w10 + dz * w20;
        float t1 = b1 + dx * w01 + dy * w11 + dz * w21;
        float t2 = b2 + dx * w02 + dy * w12 + dz * w22;
        a0 += t0; q0 = fmaf(t0, t0, q0);
        a1 += t1; q1 = fmaf(t1, t1, q1);
        a2 += t2; q2 = fmaf(t2, t2, q2);
    }
#pragma unroll
    for (int o = 16; o; o >>= 1) {
        a0 += __shfl_down_sync(0xffffffffu, a0, o);
        a1 += __shfl_down_sync(0xffffffffu, a1, o);
        a2 += __shfl_down_sync(0xffffffffu, a2, o);
        q0 += __shfl_down_sync(0xffffffffu, q0, o);
        q1 += __shfl_down_sync(0xffffffffu, q1, o);
        q2 += __shfl_down_sync(0xffffffffu, q2, o);
    }
    if ((c & 31) == 0) {
        atomicAdd(&ss[0], a0); atomicAdd(&sq[0], q0);
        atomicAdd(&ss[1], a1); atomicAdd(&sq[1], q1);
        atomicAdd(&ss[2], a2); atomicAdd(&sq[2], q2);
    }
    __syncthreads();
    if (c < 3) {
        atomicAdd(&g_sum[c], (double)ss[c]);
        atomicAdd(&g_sqs[c], (double)sq[c]);
    }
}

// ---------------- k_p2: bn2 stats over r_qk (fp16 xk gathers) ----------------
__global__ __launch_bounds__(256) void k_p2(
    const int* __restrict__ idx,
    const float* __restrict__ Wp1, const float* __restrict__ bp1,
    const float* __restrict__ Wp2, const float* __restrict__ bp2,
    const float* __restrict__ gp, const float* __restrict__ betap) {
    __shared__ __align__(16) float s_wp2[3][CCH];
    __shared__ __align__(16) float s_bp2[CCH];
    __shared__ float s_sum[CCH], s_sq[CCH];
    __shared__ __align__(16) float4 s_uj[8][32];
    __shared__ float s_a1[4], s_c1[4];
    int tid = threadIdx.x;
    bn_to_shared(0, 3, gp, betap, s_a1, s_c1);
    if (tid < CCH) {
        s_wp2[0][tid] = Wp2[tid];
        s_wp2[1][tid] = Wp2[CCH + tid];
        s_wp2[2][tid] = Wp2[2 * CCH + tid];
        s_bp2[tid] = bp2[tid];
        s_sum[tid] = 0.f; s_sq[tid] = 0.f;
    }
    float w00 = Wp1[0], w01 = Wp1[1], w02 = Wp1[2];
    float w10 = Wp1[3], w11 = Wp1[4], w12 = Wp1[5];
    float w20 = Wp1[6], w21 = Wp1[7], w22 = Wp1[8];
    float b0 = bp1[0], b1 = bp1[1], b2 = bp1[2];
    __syncthreads();
    int warp = tid >> 5, lane = tid & 31;
    int base = blockIdx.x * 256 + warp * 32;   // 32 rows = 2 points
    // phase A: own row -> u, j in smem
    {
        int row = base + lane;
        int j_own = idx[row];
        float4 pj = g_p4[j_own];
        float4 pn = g_p4[row >> 4];
        float dx = pj.x - pn.x, dy = pj.y - pn.y, dz = pj.z - pn.z;
        float t0 = b0 + dx * w00 + dy * w10 + dz * w20;
        float t1 = b1 + dx * w01 + dy * w11 + dz * w21;
        float t2 = b2 + dx * w02 + dy * w12 + dz * w22;
        float u0 = fmaxf(fmaf(s_a1[0], t0, s_c1[0]), 0.f);
        float u1 = fmaxf(fmaf(s_a1[1], t1, s_c1[1]), 0.f);
        float u2 = fmaxf(fmaf(s_a1[2], t2, s_c1[2]), 0.f);
        s_uj[warp][lane] = make_float4(u0, u1, u2, __int_as_float(j_own));
    }
    __syncwarp();
    // phase B: half-warp per point; lane owns channels cb..cb+3 (LDG.64 fp16)
    int half = lane >> 4;
    int cb = (lane & 15) * 4;
    int n0 = (base >> 4) + half;
    float4 wp0 = *reinterpret_cast<const float4*>(&s_wp2[0][cb]);
    float4 wp1 = *reinterpret_cast<const float4*>(&s_wp2[1][cb]);
    float4 wp2 = *reinterpret_cast<const float4*>(&s_wp2[2][cb]);
    float4 bbv = *reinterpret_cast<const float4*>(&s_bp2[cb]);
    {
        float4 qv = *reinterpret_cast<const float4*>(&g_xq[n0 * CCH + cb]);
        bbv.x -= qv.x; bbv.y -= qv.y; bbv.z -= qv.z; bbv.w -= qv.w;
    }
    float4 sum = make_float4(0.f, 0.f, 0.f, 0.f);
    float4 sq  = make_float4(0.f, 0.f, 0.f, 0.f);
#pragma unroll
    for (int r2 = 0; r2 < 16; r2++) {
        float4 uj = s_uj[warp][half * 16 + r2];
        int jr = __float_as_int(uj.w);
        float4 xk = ld_half4(&g_xk16[jr * CCH + cb]);
        float r0 = xk.x + fmaf(uj.x, wp0.x, fmaf(uj.y, wp1.x, fmaf(uj.z, wp2.x, bbv.x)));
        float r1 = xk.y + fmaf(uj.x, wp0.y, fmaf(uj.y, wp1.y, fmaf(uj.z, wp2.y, bbv.y)));
        float r2v= xk.z + fmaf(uj.x, wp0.z, fmaf(uj.y, wp1.z, fmaf(uj.z, wp2.z, bbv.z)));
        float r3 = xk.w + fmaf(uj.x, wp0.w, fmaf(uj.y, wp1.w, fmaf(uj.z, wp2.w, bbv.w)));
        sum.x += r0;  sq.x = fmaf(r0, r0, sq.x);
        sum.y += r1;  sq.y = fmaf(r1, r1, sq.y);
        sum.z += r2v; sq.z = fmaf(r2v, r2v, sq.z);
        sum.w += r3;  sq.w = fmaf(r3, r3, sq.w);
    }
    atomicAdd(&s_sum[cb],     sum.x); atomicAdd(&s_sq[cb],     sq.x);
    atomicAdd(&s_sum[cb + 1], sum.y); atomicAdd(&s_sq[cb + 1], sq.y);
    atomicAdd(&s_sum[cb + 2], sum.z); atomicAdd(&s_sq[cb + 2], sq.z);
    atomicAdd(&s_sum[cb + 3], sum.w); atomicAdd(&s_sq[cb + 3], sq.w);
    __syncthreads();
    if (tid < CCH) {
        atomicAdd(&g_sum[BN2_OFF + tid], (double)s_sum[tid]);
        atomicAdd(&g_sqs[BN2_OFF + tid], (double)s_sq[tid]);
    }
}

// ------- k_p3: w1 = relu(bn2(r_qk)) @ Ww1 + bww1 via mma.sync + bn3 stats ----
__global__ __launch_bounds__(128, 8) void k_p3(
    const int* __restrict__ idx,
    const float* __restrict__ Wp1, const float* __restrict__ bp1,
    const float* __restrict__ Wp2, const float* __restrict__ bp2,
    const float* __restrict__ Ww1, const float* __restrict__ bww1,
    const float* __restrict__ gp, const float* __restrict__ betap,
    const float* __restrict__ gw1, const float* __restrict__ bw1) {
    __shared__ __align__(16) __half s_h[4][16][72];   // fp16 h, 144B row stride
    __shared__ __align__(16) float s_ww1[CCH * CWCH];
    __shared__ __align__(16) float s_wp2[3][CCH];
    __shared__ __align__(16) float s_bp2[CCH];
    __shared__ float s_ws[8], s_wq[8];
    __shared__ __align__(16) float4 s_uj[4][32];
    __shared__ float s_a1[4], s_c1[4];
    __shared__ __align__(16) float s_a2[CCH];
    __shared__ __align__(16) float s_c2[CCH];
    int tid = threadIdx.x;
    bn_to_shared(0, 3, gp, betap, s_a1, s_c1);
    bn_to_shared(BN2_OFF, CCH, gw1, bw1, s_a2, s_c2);
    for (int i = tid; i < CCH * CWCH; i += 128) s_ww1[i] = Ww1[i];
    if (tid < CCH) {
        s_wp2[0][tid] = Wp2[tid];
        s_wp2[1][tid] = Wp2[CCH + tid];
        s_wp2[2][tid] = Wp2[2 * CCH + tid];
        s_bp2[tid] = bp2[tid];
    }
    if (tid < 8) { s_ws[tid] = 0.f; s_wq[tid] = 0.f; }
    __syncthreads();
    int warp = tid >> 5, lane = tid & 31;
    int base = blockIdx.x * 128 + warp * 32;
    // phase A: all 32 rows of this warp
    {
        int row = base + lane;
        int j_own = idx[row];
        float4 pj = g_p4[j_own];
        float4 pn = g_p4[row >> 4];
        float dx = pj.x - pn.x, dy = pj.y - pn.y, dz = pj.z - pn.z;
        float t0 = bp1[0] + dx * Wp1[0] + dy * Wp1[3] + dz * Wp1[6];
        float t1 = bp1[1] + dx * Wp1[1] + dy * Wp1[4] + dz * Wp1[7];
        float t2 = bp1[2] + dx * Wp1[2] + dy * Wp1[5] + dz * Wp1[8];
        float u0 = fmaxf(fmaf(s_a1[0], t0, s_c1[0]), 0.f);
        float u1 = fmaxf(fmaf(s_a1[1], t1, s_c1[1]), 0.f);
        float u2 = fmaxf(fmaf(s_a1[2], t2, s_c1[2]), 0.f);
        s_uj[warp][lane] = make_float4(u0, u1, u2, __int_as_float(j_own));
    }
    __syncwarp();

    // B fragments (Ww1 -> fp16, per-lane mma layout), built once
    int t2 = (lane & 3) * 2;      // accumulator/B k&col sub-index *2
    int qn = lane >> 2;           // group id (n for B, row for C)
    uint32_t bf0[4], bf1[4];
#pragma unroll
    for (int kc = 0; kc < 4; kc++) {
        __half2 x0 = __floats2half2_rn(s_ww1[(kc * 16 + t2) * 8 + qn],
                                       s_ww1[(kc * 16 + t2 + 1) * 8 + qn]);
        __half2 x1 = __floats2half2_rn(s_ww1[(kc * 16 + t2 + 8) * 8 + qn],
                                       s_ww1[(kc * 16 + t2 + 9) * 8 + qn]);
        bf0[kc] = *reinterpret_cast<uint32_t*>(&x0);
        bf1[kc] = *reinterpret_cast<uint32_t*>(&x1);
    }
    float bias0 = bww1[t2], bias1 = bww1[t2 + 1];

#pragma unroll
    for (int tile = 0; tile < 2; tile++) {
        // phase B: one point (16 rows); half-warp covers 8 rows; lane owns 4 ch
        {
            int half = lane >> 4;
            int cb = (lane & 15) * 4;
            int nt = (base >> 4) + tile;
            float4 a2 = *reinterpret_cast<const float4*>(&s_a2[cb]);
            float4 c2 = *reinterpret_cast<const float4*>(&s_c2[cb]);
            float4 wp0 = *reinterpret_cast<const float4*>(&s_wp2[0][cb]);
            float4 wp1 = *reinterpret_cast<const float4*>(&s_wp2[1][cb]);
            float4 wp2 = *reinterpret_cast<const float4*>(&s_wp2[2][cb]);
            float4 bbv = *reinterpret_cast<const float4*>(&s_bp2[cb]);
            {
                float4 qv = *reinterpret_cast<const float4*>(&g_xq[nt * CCH + cb]);
                bbv.x -= qv.x; bbv.y -= qv.y; bbv.z -= qv.z; bbv.w -= qv.w;
            }
#pragma unroll
            for (int r2 = 0; r2 < 8; r2++) {
                int r = half * 8 + r2;
                float4 uj = s_uj[warp][tile * 16 + r];
                int jr = __float_as_int(uj.w);
                float4 xk = ld_half4(&g_xk16[jr * CCH + cb]);
                float r0 = xk.x + fmaf(uj.x, wp0.x, fmaf(uj.y, wp1.x, fmaf(uj.z, wp2.x, bbv.x)));
                float r1 = xk.y + fmaf(uj.x, wp0.y, fmaf(uj.y, wp1.y, fmaf(uj.z, wp2.y, bbv.y)));
                float r2v= xk.z + fmaf(uj.x, wp0.z, fmaf(uj.y, wp1.z, fmaf(uj.z, wp2.z, bbv.z)));
                float r3 = xk.w + fmaf(uj.x, wp0.w, fmaf(uj.y, wp1.w, fmaf(uj.z, wp2.w, bbv.w)));
                __half2 ha = __floats2half2_rn(fmaxf(fmaf(a2.x, r0, c2.x), 0.f),
                                               fmaxf(fmaf(a2.y, r1, c2.y), 0.f));
                __half2 hb = __floats2half2_rn(fmaxf(fmaf(a2.z, r2v, c2.z), 0.f),
                                               fmaxf(fmaf(a2.w, r3, c2.w), 0.f));
                uint2 pk;
                pk.x = *reinterpret_cast<uint32_t*>(&ha);
                pk.y = *reinterpret_cast<uint32_t*>(&hb);
                *reinterpret_cast<uint2*>(&s_h[warp][r][cb]) = pk;
            }
        }
        __syncwarp();
        // phase C: 16x8x64 matmul via 4 chained mma.sync.m16n8k16
        {
            float c0 = bias0, c1 = bias1, c2 = bias0, c3 = bias1;
            int arow = lane & 15;
            int acol = (lane >> 4) * 8;
#pragma unroll
            for (int kc = 0; kc < 4; kc++) {
                uint32_t a0, a1, a2r, a3;
                uint32_t addr = (uint32_t)__cvta_generic_to_shared(
                    &s_h[warp][arow][kc * 16 + acol]);
                asm volatile(
                    "ldmatrix.sync.aligned.m8n8.x4.shared.b16 {%0,%1,%2,%3}, [%4];"
                    : "=r"(a0), "=r"(a1), "=r"(a2r), "=r"(a3) : "r"(addr));
                asm volatile(
                    "mma.sync.aligned.m16n8k16.row.col.f32.f16.f16.f32 "
                    "{%0,%1,%2,%3}, {%4,%5,%6,%7}, {%8,%9}, {%0,%1,%2,%3};"
                    : "+f"(c0), "+f"(c1), "+f"(c2), "+f"(c3)
                    : "r"(a0), "r"(a1), "r"(a2r), "r"(a3),
                      "r"(bf0[kc]), "r"(bf1[kc]));
            }
            int row0 = base + tile * 16 + qn;
            *reinterpret_cast<float2*>(&g_w1[row0 * 8 + t2]) = make_float2(c0, c1);
            *reinterpret_cast<float2*>(&g_w1[(row0 + 8) * 8 + t2]) = make_float2(c2, c3);
            // bn3 stats: reduce over rows (lane bits 2..4)
            float s0 = c0 + c2, q0 = c0 * c0 + c2 * c2;
            float s1 = c1 + c3, q1 = c1 * c1 + c3 * c3;
#pragma unroll
            for (int o = 4; o <= 16; o <<= 1) {
                s0 += __shfl_xor_sync(0xffffffffu, s0, o);
                q0 += __shfl_xor_sync(0xffffffffu, q0, o);
                s1 += __shfl_xor_sync(0xffffffffu, s1, o);
                q1 += __shfl_xor_sync(0xffffffffu, q1, o);
            }
            if (lane < 4) {
                atomicAdd(&s_ws[t2], s0);     atomicAdd(&s_wq[t2], q0);
                atomicAdd(&s_ws[t2 + 1], s1); atomicAdd(&s_wq[t2 + 1], q1);
            }
        }
        __syncwarp();
    }
    __syncthreads();
    if (tid < 8) {
        atomicAdd(&g_sum[BN3_OFF + tid], (double)s_ws[tid]);
        atomicAdd(&g_sqs[BN3_OFF + tid], (double)s_wq[tid]);
    }
}

// ---------------- k_p4: bn3 + 8x8 + softmax + weighted sum -> out ----------
__global__ __launch_bounds__(256) void k_p4(
    const int* __restrict__ idx,
    const float* __restrict__ Wp1, const float* __restrict__ bp1,
    const float* __restrict__ Wp2, const float* __restrict__ bp2,
    const float* __restrict__ Ww2, const float* __restrict__ bww2,
    const float* __restrict__ gp, const float* __restrict__ betap,
    const float* __restrict__ gw2, const float* __restrict__ bw2,
    float* __restrict__ out) {
    __shared__ float s_wp2[3][CCH], s_bp2[CCH];
    __shared__ float s_ww2[64];
    __shared__ float s_bww2[8];
    __shared__ __align__(16) float s_w[16][16][8];
    __shared__ __align__(16) float4 s_t1r[16][16];   // {u0,u1,u2, j bits}
    __shared__ float s_a1[4], s_c1[4], s_a3[8], s_c3[8];
    int tid = threadIdx.x;
    bn_to_shared(0, 3, gp, betap, s_a1, s_c1);
    bn_to_shared(BN3_OFF, 8, gw2, bw2, s_a3, s_c3);
    if (tid < CCH) {
        s_wp2[0][tid] = Wp2[tid];
        s_wp2[1][tid] = Wp2[CCH + tid];
        s_wp2[2][tid] = Wp2[2 * CCH + tid];
        s_bp2[tid] = bp2[tid];
        s_ww2[tid] = Ww2[tid];
    }
    if (tid < 8) s_bww2[tid] = bww2[tid];
    __syncthreads();

    int gl = tid & 15;
    int pt = tid >> 4;
    int n = blockIdx.x * 16 + pt;
    int row = n * NSAMP + gl;
    int j = idx[row];

    float4 pj = g_p4[j];
    float4 pn = g_p4[n];
    float dx = pj.x - pn.x, dy = pj.y - pn.y, dz = pj.z - pn.z;
    float t0 = bp1[0] + dx * Wp1[0] + dy * Wp1[3] + dz * Wp1[6];
    float t1 = bp1[1] + dx * Wp1[1] + dy * Wp1[4] + dz * Wp1[7];
    float t2 = bp1[2] + dx * Wp1[2] + dy * Wp1[5] + dz * Wp1[8];
    float u0 = fmaxf(fmaf(s_a1[0], t0, s_c1[0]), 0.f);
    float u1 = fmaxf(fmaf(s_a1[1], t1, s_c1[1]), 0.f);
    float u2 = fmaxf(fmaf(s_a1[2], t2, s_c1[2]), 0.f);
    s_t1r[pt][gl] = make_float4(u0, u1, u2, __int_as_float(j));

    float4 wa = *reinterpret_cast<const float4*>(&g_w1[row * 8]);
    float4 wb = *reinterpret_cast<const float4*>(&g_w1[row * 8 + 4]);
    float v1[8] = {wa.x, wa.y, wa.z, wa.w, wb.x, wb.y, wb.z, wb.w};
    float uu[8];
#pragma unroll
    for (int k = 0; k < 8; k++)
        uu[k] = fmaxf(fmaf(s_a3[k], v1[k], s_c3[k]), 0.f);
    float w2[8];
#pragma unroll
    for (int k2 = 0; k2 < 8; k2++) {
        float acc = s_bww2[k2];
#pragma unroll
        for (int k = 0; k < 8; k++) acc = fmaf(uu[k], s_ww2[k * 8 + k2], acc);
        w2[k2] = acc;
    }
#pragma unroll
    for (int k2 = 0; k2 < 8; k2++) {
        float mx = w2[k2];
        mx = fmaxf(mx, __shfl_xor_sync(0xffffffffu, mx, 1));
        mx = fmaxf(mx, __shfl_xor_sync(0xffffffffu, mx, 2));
        mx = fmaxf(mx, __shfl_xor_sync(0xffffffffu, mx, 4));
        mx = fmaxf(mx, __shfl_xor_sync(0xffffffffu, mx, 8));
        float e = __expf(w2[k2] - mx);
        float s = e;
        s += __shfl_xor_sync(0xffffffffu, s, 1);
        s += __shfl_xor_sync(0xffffffffu, s, 2);
        s += __shfl_xor_sync(0xffffffffu, s, 4);
        s += __shfl_xor_sync(0xffffffffu, s, 8);
        w2[k2] = e / s;
    }
    *reinterpret_cast<float4*>(&s_w[pt][gl][0]) = make_float4(w2[0], w2[1], w2[2], w2[3]);
    *reinterpret_cast<float4*>(&s_w[pt][gl][4]) = make_float4(w2[4], w2[5], w2[6], w2[7]);
    __syncwarp();

    int cb = gl * 4;
    int kb = (gl & 1) * 4;
    float wp0x = s_wp2[0][cb],     wp1x = s_wp2[1][cb],     wp2x = s_wp2[2][cb],     bv0 = s_bp2[cb];
    float wp0y = s_wp2[0][cb + 1], wp1y = s_wp2[1][cb + 1], wp2y = s_wp2[2][cb + 1], bv1 = s_bp2[cb + 1];
    float wp0z = s_wp2[0][cb + 2], wp1z = s_wp2[1][cb + 2], wp2z = s_wp2[2][cb + 2], bv2 = s_bp2[cb + 2];
    float wp0w = s_wp2[0][cb + 3], wp1w = s_wp2[1][cb + 3], wp2w = s_wp2[2][cb + 3], bv3 = s_bp2[cb + 3];
    float o0 = 0.f, o1 = 0.f, o2 = 0.f, o3 = 0.f;
#pragma unroll
    for (int t = 0; t < NSAMP; t++) {
        float4 tj = s_t1r[pt][t];
        int jt = __float_as_int(tj.w);
        float4 xv = ld_half4(&g_xv16[jt * CCH + cb]);
        float4 wt = *reinterpret_cast<const float4*>(&s_w[pt][t][kb]);
        float pr0 = bv0 + tj.x * wp0x + tj.y * wp1x + tj.z * wp2x;
        float pr1 = bv1 + tj.x * wp0y + tj.y * wp1y + tj.z * wp2y;
        float pr2 = bv2 + tj.x * wp0z + tj.y * wp1z + tj.z * wp2z;
        float pr3 = bv3 + tj.x * wp0w + tj.y * wp1w + tj.z * wp2w;
        o0 = fmaf(xv.x + pr0, wt.x, o0);
        o1 = fmaf(xv.y + pr1, wt.y, o1);
        o2 = fmaf(xv.z + pr2, wt.z, o2);
        o3 = fmaf(xv.w + pr3, wt.w, o3);
    }
    *reinterpret_cast<float4*>(&out[n * CCH + cb]) = make_float4(o0, o1, o2, o3);
}

// ---------------- launch ----------------
extern "C" void kernel_launch(void* const* d_in, const int* in_sizes, int n_in,
                              void* d_out, int out_size) {
    const float* p    = (const float*)d_in[0];
    const float* x    = (const float*)d_in[1];
    const int*   idx  = (const int*)  d_in[3];
    const float* Wq   = (const float*)d_in[4];
    const float* bq   = (const float*)d_in[5];
    const float* Wk   = (const float*)d_in[6];
    const float* bk   = (const float*)d_in[7];
    const float* Wv   = (const float*)d_in[8];
    const float* bv   = (const float*)d_in[9];
    const float* Wp1  = (const float*)d_in[10];
    const float* bp1  = (const float*)d_in[11];
    const float* gp   = (const float*)d_in[12];
    const float* betap= (const float*)d_in[13];
    const float* Wp2  = (const float*)d_in[14];
    const float* bp2  = (const float*)d_in[15];
    const float* gw1  = (const float*)d_in[16];
    const float* bw1  = (const float*)d_in[17];
    const float* Ww1  = (const float*)d_in[18];
    const float* bww1 = (const float*)d_in[19];
    const float* gw2  = (const float*)d_in[20];
    const float* bw2  = (const float*)d_in[21];
    const float* Ww2  = (const float*)d_in[22];
    const float* bww2 = (const float*)d_in[23];
    float* out = (float*)d_out;

    k_pad<<<(NPTS + 255) / 256, 256>>>(p);                                   // 0
    k_qkv<<<QKV_GRID, QKV_THREADS>>>(x, idx, Wq, bq, Wk, bk, Wv, bv,
                                     Wp1, bp1);                              // 1
    k_p2<<<NROW / 256, 256>>>(idx, Wp1, bp1, Wp2, bp2, gp, betap);           // 2
    k_p3<<<NROW / 128, 128>>>(idx, Wp1, bp1, Wp2, bp2, Ww1, bww1,
                              gp, betap, gw1, bw1);                          // 3 <- profiled
    k_p4<<<NPTS / 16, 256>>>(idx, Wp1, bp1, Wp2, bp2, Ww2, bww2,
                             gp, betap, gw2, bw2, out);                      // 4
}